// round 16
// baseline (speedup 1.0000x reference)
#include <cuda_runtime.h>
#include <cuda_bf16.h>
#include <cstdint>

// ---------------------------------------------------------------------------
// PointNet++ encoder on GB300 (base sm_103 PTX: mma.sync + cp.async only).
// FPS / ball-query: exact fp32 (bitwise-match indices vs JAX ref).
// MLP: mma.sync m16n8k16 bf16, 3-term fp32 emulation (hi/lo bf16 split).
// R16: BN=64 tiles + ST=36 stride -> 55KB smem, ~80 regs -> 4 CTAs/SM.
// Producer fusion: ballq1 emits gathered rows; K=3 layer fused into L1_1;
// stage-2 gather fused into L2_0 prefetch. Pools fused into final layers.
// ---------------------------------------------------------------------------

#define BB   32
#define N1   4096
#define S1   256
#define S2   128
#define NS   32
#define ST   36     // smem row stride (floats): conflict-free float2 frags

__device__ float g_scr0[262144 * 128];   // 134 MB
__device__ float g_scr1[262144 * 128];   // 134 MB
__device__ float g_f1[BB * S1 * 128];
__device__ float g_f2[BB * S2 * 256];
__device__ float g_nx1[BB * S1 * 3];
__device__ float g_nx2[BB * S2 * 3];
__device__ int   g_g2[BB * S2 * NS];
__device__ float g_x3[BB * S2 * 288];
__device__ float g_w2p[128 * 160];       // reordered [f128 | xyz3 | pad29]
__device__ float g_w3p[256 * 288];

__device__ __forceinline__ uint32_t smem_u32(const void* p) {
    uint32_t a;
    asm("{ .reg .u64 t; cvta.to.shared.u64 t, %1; cvt.u32.u64 %0, t; }"
        : "=r"(a) : "l"(p));
    return a;
}
__device__ __forceinline__ void cp16(uint32_t dst, const void* src) {
    asm volatile("cp.async.ca.shared.global [%0], [%1], 16;"
                 :: "r"(dst), "l"(src) : "memory");
}
#define CP_COMMIT() asm volatile("cp.async.commit_group;" ::: "memory")
#define CP_WAIT0()  asm volatile("cp.async.wait_group 0;" ::: "memory")
#define CP_WAIT1()  asm volatile("cp.async.wait_group 1;" ::: "memory")
#define CP_WAIT2()  asm volatile("cp.async.wait_group 2;" ::: "memory")

#define MMA_BF16(c, a, b0, b1)                                                \
    asm volatile(                                                             \
        "mma.sync.aligned.m16n8k16.row.col.f32.bf16.bf16.f32 "                \
        "{%0,%1,%2,%3}, {%4,%5,%6,%7}, {%8,%9}, {%0,%1,%2,%3};"               \
        : "+f"((c)[0]), "+f"((c)[1]), "+f"((c)[2]), "+f"((c)[3])              \
        : "r"((a)[0]), "r"((a)[1]), "r"((a)[2]), "r"((a)[3]),                 \
          "r"(b0), "r"(b1))

// Split a float pair into packed bf16x2 hi and lo (x in low half = even k).
__device__ __forceinline__ void split_pair(float x, float y,
                                           uint32_t& hi, uint32_t& lo)
{
    __nv_bfloat162 h = __floats2bfloat162_rn(x, y);
    float hx = __bfloat162float(__low2bfloat16(h));
    float hy = __bfloat162float(__high2bfloat16(h));
    __nv_bfloat162 l = __floats2bfloat162_rn(x - hx, y - hy);
    hi = *reinterpret_cast<uint32_t*>(&h);
    lo = *reinterpret_cast<uint32_t*>(&l);
}

// A fragment (m16n8k16, 2 m-tiles) for one k16 group starting at column kb.
__device__ __forceinline__ void frag_a_bf16(
    const float* s_a, int wm, int g, int tg, int kb,
    uint32_t ah[2][4], uint32_t al[2][4])
{
#pragma unroll
    for (int mt = 0; mt < 2; mt++) {
        int r0 = wm + mt * 16 + g;
        float2 p0 = *reinterpret_cast<const float2*>(&s_a[r0 * ST + kb + 2 * tg]);
        float2 p1 = *reinterpret_cast<const float2*>(&s_a[(r0 + 8) * ST + kb + 2 * tg]);
        float2 p2 = *reinterpret_cast<const float2*>(&s_a[r0 * ST + kb + 2 * tg + 8]);
        float2 p3 = *reinterpret_cast<const float2*>(&s_a[(r0 + 8) * ST + kb + 2 * tg + 8]);
        split_pair(p0.x, p0.y, ah[mt][0], al[mt][0]);
        split_pair(p1.x, p1.y, ah[mt][1], al[mt][1]);
        split_pair(p2.x, p2.y, ah[mt][2], al[mt][2]);
        split_pair(p3.x, p3.y, ah[mt][3], al[mt][3]);
    }
}

// B fragment split + 3-term emulated mma applied to both m-tiles.
__device__ __forceinline__ void bfrag_mma_bf16(
    const float* s_w, int n, int kb, int tg,
    const uint32_t ah[2][4], const uint32_t al[2][4],
    float* acc0, float* acc1)
{
    float2 q0 = *reinterpret_cast<const float2*>(&s_w[n * ST + kb + 2 * tg]);
    float2 q1 = *reinterpret_cast<const float2*>(&s_w[n * ST + kb + 2 * tg + 8]);
    uint32_t bh0, bl0, bh1, bl1;
    split_pair(q0.x, q0.y, bh0, bl0);
    split_pair(q1.x, q1.y, bh1, bl1);
    MMA_BF16(acc0, ah[0], bh0, bh1);
    MMA_BF16(acc0, ah[0], bl0, bl1);
    MMA_BF16(acc0, al[0], bh0, bh1);
    MMA_BF16(acc1, ah[1], bh0, bh1);
    MMA_BF16(acc1, ah[1], bl0, bl1);
    MMA_BF16(acc1, al[1], bh0, bh1);
}

// ---------------------------------------------------------------------------
// FPS stage 1 (bitwise exact vs reference)
// ---------------------------------------------------------------------------
template <int N, int NPTS, int THREADS>
__global__ void __launch_bounds__(THREADS) fps_kernel(
    const float* __restrict__ xyz_all, float* __restrict__ new_xyz)
{
    constexpr int PPT = N / THREADS;
    const int b = blockIdx.x;
    const int t = threadIdx.x;
    const float* xyz = xyz_all + (size_t)b * N * 3;

    float px[PPT], py[PPT], pz[PPT], md[PPT];
#pragma unroll
    for (int j = 0; j < PPT; j++) {
        int i = t + j * THREADS;
        px[j] = xyz[i * 3 + 0];
        py[j] = xyz[i * 3 + 1];
        pz[j] = xyz[i * 3 + 2];
        md[j] = 1e10f;
    }

    __shared__ unsigned long long wred[THREADS / 32];
    __shared__ int s_last;

    int last = 0;
    for (int it = 0; it < NPTS; it++) {
        float lx = __ldg(&xyz[last * 3 + 0]);
        float ly = __ldg(&xyz[last * 3 + 1]);
        float lz = __ldg(&xyz[last * 3 + 2]);
        if (t == 0) {
            float* o = new_xyz + (size_t)(b * NPTS + it) * 3;
            o[0] = lx; o[1] = ly; o[2] = lz;
        }
        unsigned long long best = 0ull;
#pragma unroll
        for (int j = 0; j < PPT; j++) {
            float dx = px[j] - lx, dy = py[j] - ly, dz = pz[j] - lz;
            float d = __fadd_rn(__fadd_rn(__fmul_rn(dx, dx), __fmul_rn(dy, dy)),
                                __fmul_rn(dz, dz));
            float m = fminf(md[j], d);
            md[j] = m;
            unsigned long long key =
                (((unsigned long long)__float_as_uint(m)) << 32) |
                (unsigned)(0xFFFFFFFFu - (unsigned)(t + j * THREADS));
            best = (key > best) ? key : best;
        }
#pragma unroll
        for (int off = 16; off > 0; off >>= 1) {
            unsigned long long o = __shfl_down_sync(0xffffffffu, best, off);
            best = (o > best) ? o : best;
        }
        if ((t & 31) == 0) wred[t >> 5] = best;
        __syncthreads();
        if (t < 32) {
            unsigned long long v = (t < THREADS / 32) ? wred[t] : 0ull;
#pragma unroll
            for (int off = 16; off > 0; off >>= 1) {
                unsigned long long o = __shfl_down_sync(0xffffffffu, v, off);
                v = (o > v) ? o : v;
            }
            if (t == 0)
                s_last = (int)(0xFFFFFFFFu - (unsigned)(v & 0xFFFFFFFFull));
        }
        __syncthreads();
        last = s_last;
    }
}

// ---------------------------------------------------------------------------
// Stage-1 ball query + gather
// ---------------------------------------------------------------------------
__global__ void __launch_bounds__(1024) ballq1_gather(
    const float* __restrict__ xyz_all, const float* __restrict__ centers,
    float R2, float* __restrict__ xg)
{
    extern __shared__ float sm[];
    float* sx = sm;
    float* sy = sm + N1;
    float* sz = sm + 2 * N1;
    int* buf = (int*)(sm + 3 * N1);          // [32][32]

    const int b = blockIdx.x >> 3;
    const int grp = blockIdx.x & 7;
    const float* xyz = xyz_all + (size_t)b * N1 * 3;
    for (int i = threadIdx.x; i < N1; i += 1024) {
        sx[i] = xyz[i * 3 + 0];
        sy[i] = xyz[i * 3 + 1];
        sz[i] = xyz[i * 3 + 2];
    }
    __syncthreads();

    const int wid = threadIdx.x >> 5, lane = threadIdx.x & 31;
    int* mybuf = buf + wid * 32;
    const int s = grp * 32 + wid;
    const int gw = b * S1 + s;
    const float cx = centers[gw * 3 + 0];
    const float cy = centers[gw * 3 + 1];
    const float cz = centers[gw * 3 + 2];
    int cnt = 0;
    for (int base = 0; base < N1; base += 32) {
        int p = base + lane;
        float dx = sx[p] - cx;
        float dy = sy[p] - cy;
        float dz = sz[p] - cz;
        float d2 = __fadd_rn(__fadd_rn(__fmul_rn(dx, dx), __fmul_rn(dy, dy)),
                             __fmul_rn(dz, dz));
        bool pred = d2 < R2;
        unsigned mask = __ballot_sync(0xffffffffu, pred);
        if (pred) {
            int pos = cnt + __popc(mask & ((1u << lane) - 1u));
            if (pos < NS) mybuf[pos] = p;
        }
        cnt += __popc(mask);
        if (cnt >= NS) break;
    }
    __syncwarp();
    int nv = cnt < NS ? cnt : NS;
    int first = (cnt > 0) ? mybuf[0] : 0;
    int val = (lane < nv) ? mybuf[lane] : first;
    float4 o;
    o.x = sx[val] - cx;
    o.y = sy[val] - cy;
    o.z = sz[val] - cz;
    o.w = 0.f;
    *reinterpret_cast<float4*>(xg + ((size_t)gw * 32 + lane) * 4) = o;
}

// ---------------------------------------------------------------------------
// Fused FPS stage 2 + ball query 2
// ---------------------------------------------------------------------------
__global__ void __launch_bounds__(256) fps2_ballq2(
    const float* __restrict__ xyz_all, float* __restrict__ new_xyz,
    float R2, int* __restrict__ out)
{
    __shared__ float s_px[S1], s_py[S1], s_pz[S1];
    __shared__ float s_cx[S2], s_cy[S2], s_cz[S2];
    __shared__ unsigned long long wred[8];
    __shared__ int s_last;
    __shared__ int buf[8][32];

    const int b = blockIdx.x;
    const int t = threadIdx.x;
    const float* xyz = xyz_all + (size_t)b * S1 * 3;

    float px = xyz[t * 3 + 0];
    float py = xyz[t * 3 + 1];
    float pz = xyz[t * 3 + 2];
    s_px[t] = px; s_py[t] = py; s_pz[t] = pz;
    float md = 1e10f;

    int last = 0;
    for (int it = 0; it < S2; it++) {
        float lx = __ldg(&xyz[last * 3 + 0]);
        float ly = __ldg(&xyz[last * 3 + 1]);
        float lz = __ldg(&xyz[last * 3 + 2]);
        if (t == 0) {
            float* o = new_xyz + (size_t)(b * S2 + it) * 3;
            o[0] = lx; o[1] = ly; o[2] = lz;
            s_cx[it] = lx; s_cy[it] = ly; s_cz[it] = lz;
        }
        float dx = px - lx, dy = py - ly, dz = pz - lz;
        float d = __fadd_rn(__fadd_rn(__fmul_rn(dx, dx), __fmul_rn(dy, dy)),
                            __fmul_rn(dz, dz));
        md = fminf(md, d);
        unsigned long long best =
            (((unsigned long long)__float_as_uint(md)) << 32) |
            (unsigned)(0xFFFFFFFFu - (unsigned)t);
#pragma unroll
        for (int off = 16; off > 0; off >>= 1) {
            unsigned long long o = __shfl_down_sync(0xffffffffu, best, off);
            best = (o > best) ? o : best;
        }
        if ((t & 31) == 0) wred[t >> 5] = best;
        __syncthreads();
        if (t < 32) {
            unsigned long long v = (t < 8) ? wred[t] : 0ull;
#pragma unroll
            for (int off = 16; off > 0; off >>= 1) {
                unsigned long long o = __shfl_down_sync(0xffffffffu, v, off);
                v = (o > v) ? o : v;
            }
            if (t == 0)
                s_last = (int)(0xFFFFFFFFu - (unsigned)(v & 0xFFFFFFFFull));
        }
        __syncthreads();
        last = s_last;
    }

    const int wid = t >> 5, lane = t & 31;
    int* mybuf = buf[wid];
    for (int ci = 0; ci < 16; ci++) {
        const int s = wid * 16 + ci;
        const float cx = s_cx[s], cy = s_cy[s], cz = s_cz[s];
        int cnt = 0;
        for (int base = 0; base < S1; base += 32) {
            int p = base + lane;
            float dx = s_px[p] - cx;
            float dy = s_py[p] - cy;
            float dz = s_pz[p] - cz;
            float d2 = __fadd_rn(__fadd_rn(__fmul_rn(dx, dx), __fmul_rn(dy, dy)),
                                 __fmul_rn(dz, dz));
            bool pred = d2 < R2;
            unsigned mask = __ballot_sync(0xffffffffu, pred);
            if (pred) {
                int pos = cnt + __popc(mask & ((1u << lane) - 1u));
                if (pos < NS) mybuf[pos] = p;
            }
            cnt += __popc(mask);
            if (cnt >= NS) break;
        }
        __syncwarp();
        int nv = cnt < NS ? cnt : NS;
        int first = (cnt > 0) ? mybuf[0] : 0;
        int val = (lane < nv) ? mybuf[lane] : first;
        out[((size_t)(b * S2 + s)) * NS + lane] = val;
        __syncwarp();
    }
}

// ---------------------------------------------------------------------------
// concat3 / weight pads
// ---------------------------------------------------------------------------
__global__ void concat3_kernel(float* __restrict__ x3)
{
    int t = blockIdx.x * blockDim.x + threadIdx.x;
    if (t >= BB * S2 * 288) return;
    int r = t / 288, col = t - r * 288;
    x3[t] = (col < 3) ? g_nx2[(size_t)r * 3 + col]
                      : (col < 259 ? g_f2[(size_t)r * 256 + (col - 3)] : 0.f);
}

__global__ void padw_kernel(const float* __restrict__ w, float* __restrict__ o,
                            int n, int kin, int kout)
{
    int t = blockIdx.x * blockDim.x + threadIdx.x;
    if (t >= n * kout) return;
    int r = t / kout, c = t - r * kout;
    o[t] = (c < kin) ? w[r * kin + c] : 0.f;
}

__global__ void padw2_reorder(const float* __restrict__ w, float* __restrict__ o)
{
    int t = blockIdx.x * blockDim.x + threadIdx.x;
    if (t >= 128 * 160) return;
    int r = t / 160, c = t - r * 160;
    float v = 0.f;
    if (c < 128)      v = w[r * 131 + 3 + c];
    else if (c < 131) v = w[r * 131 + (c - 128)];
    o[t] = v;
}

// ---------------------------------------------------------------------------
// L1_1 fused
// ---------------------------------------------------------------------------
__global__ void __launch_bounds__(256) gemm_l11_fused(
    const float* __restrict__ xg,
    const float* __restrict__ w0, const float* __restrict__ b0,
    const float* __restrict__ w1, const float* __restrict__ b1,
    float* __restrict__ C)
{
    extern __shared__ float smf[];
    float* s_A = smf;
    float* s_W = smf + 2 * 128 * ST;
    float* s_x = s_W + 2 * 64 * ST;

    const int tid = threadIdx.x;
    const int wid = tid >> 5, lane = tid & 31;
    const int g = lane >> 2, tg = lane & 3;
    const int wm = (wid & 3) * 32;
    const int wn = (wid >> 2) * 32;
    const int m0 = blockIdx.x * 128;
    const uint32_t smbase = smem_u32(smf);
    const uint32_t sxoff = (uint32_t)(2 * 128 * ST + 2 * 64 * ST) * 4u;

    if (tid < 128)
        cp16(smbase + sxoff + (uint32_t)tid * 16u, xg + (size_t)(m0 + tid) * 4);
    CP_COMMIT();
#pragma unroll
    for (int kc = 0; kc < 2; kc++) {
#pragma unroll
        for (int i = 0; i < 2; i++) {
            int seg = tid + i * 256;
            int r = seg >> 3, c16 = seg & 7;
            cp16(smbase + (uint32_t)((2 * 128 * ST + kc * 64 * ST) + r * ST + c16 * 4) * 4u,
                 w1 + (size_t)r * 64 + kc * 32 + c16 * 4);
        }
        CP_COMMIT();
    }

    CP_WAIT2();
    __syncthreads();

    for (int idx = tid; idx < 128 * 64; idx += 256) {
        int r = idx >> 6, o = idx & 63;
        const float* xr = s_x + r * 4;
        float acc = 0.f;
        acc = fmaf(xr[0], __ldg(&w0[o * 3 + 0]), acc);
        acc = fmaf(xr[1], __ldg(&w0[o * 3 + 1]), acc);
        acc = fmaf(xr[2], __ldg(&w0[o * 3 + 2]), acc);
        s_A[(o >> 5) * 128 * ST + r * ST + (o & 31)] =
            fmaxf(acc + __ldg(&b0[o]), 0.f);
    }

    float acc[2][4][4];
#pragma unroll
    for (int mt = 0; mt < 2; mt++)
#pragma unroll
        for (int nt = 0; nt < 4; nt++)
#pragma unroll
            for (int j = 0; j < 4; j++) acc[mt][nt][j] = 0.f;

#pragma unroll
    for (int kc = 0; kc < 2; kc++) {
        if (kc == 0) { CP_WAIT1(); } else { CP_WAIT0(); }
        __syncthreads();
        const float* s_a = s_A + kc * 128 * ST;
        const float* s_w = s_W + kc * 64 * ST;
#pragma unroll
        for (int grp = 0; grp < 2; grp++) {
            const int kb = grp * 16;
            uint32_t ah[2][4], al[2][4];
            frag_a_bf16(s_a, wm, g, tg, kb, ah, al);
#pragma unroll
            for (int nt = 0; nt < 4; nt++) {
                int n = wn + nt * 8 + g;
                bfrag_mma_bf16(s_w, n, kb, tg, ah, al, acc[0][nt], acc[1][nt]);
            }
        }
        __syncthreads();
    }

#pragma unroll
    for (int mt = 0; mt < 2; mt++) {
#pragma unroll
        for (int nt = 0; nt < 4; nt++) {
            int row = m0 + wm + mt * 16 + g;
            int col = wn + nt * 8 + 2 * tg;
            float b0v = __ldg(&b1[col]);
            float b1v = __ldg(&b1[col + 1]);
            float2 o0, o1;
            o0.x = fmaxf(acc[mt][nt][0] + b0v, 0.f);
            o0.y = fmaxf(acc[mt][nt][1] + b1v, 0.f);
            o1.x = fmaxf(acc[mt][nt][2] + b0v, 0.f);
            o1.y = fmaxf(acc[mt][nt][3] + b1v, 0.f);
            *reinterpret_cast<float2*>(C + (size_t)row * 64 + col) = o0;
            *reinterpret_cast<float2*>(C + (size_t)(row + 8) * 64 + col) = o1;
        }
    }
}

// ---------------------------------------------------------------------------
// Generic mma mainloop (cp.async double-buffered), CTA tile 128 x BN, BK=32.
// ---------------------------------------------------------------------------
template <int BN, int NTW>
__device__ __forceinline__ void mma_mainloop(
    const float* __restrict__ A, const float* __restrict__ W,
    int K, int m0, int n0, float* smf, uint32_t smbase,
    int tid, int wid, int lane, int g, int tg, int wm, int wn,
    float acc[2][NTW][4])
{
    constexpr int SLOT = (128 + BN) * ST;
    const int KC = K >> 5;

    auto prefetch = [&](int kc, int s) {
        const uint32_t sb = smbase + (uint32_t)(s * SLOT) * 4u;
#pragma unroll
        for (int i = 0; i < 4; i++) {
            int seg = tid + i * 256;
            int r = seg >> 3, c16 = seg & 7;
            cp16(sb + (uint32_t)(r * ST + c16 * 4) * 4u,
                 A + (size_t)(m0 + r) * K + kc * 32 + c16 * 4);
        }
#pragma unroll
        for (int i = 0; i < BN / 32; i++) {
            int seg = tid + i * 256;
            int r = seg >> 3, c16 = seg & 7;
            cp16(sb + (uint32_t)((128 + r) * ST + c16 * 4) * 4u,
                 W + (size_t)(n0 + r) * K + kc * 32 + c16 * 4);
        }
    };

    prefetch(0, 0);
    CP_COMMIT();

    for (int kc = 0; kc < KC; kc++) {
        if (kc + 1 < KC) prefetch(kc + 1, (kc + 1) & 1);
        CP_COMMIT();
        CP_WAIT1();
        __syncthreads();

        const float* s_a = smf + (kc & 1) * SLOT;
        const float* s_w = s_a + 128 * ST;

#pragma unroll
        for (int grp = 0; grp < 2; grp++) {
            const int kb = grp * 16;
            uint32_t ah[2][4], al[2][4];
            frag_a_bf16(s_a, wm, g, tg, kb, ah, al);
#pragma unroll
            for (int nt = 0; nt < NTW; nt++) {
                int n = wn + nt * 8 + g;
                bfrag_mma_bf16(s_w, n, kb, tg, ah, al, acc[0][nt], acc[1][nt]);
            }
        }
        __syncthreads();
    }
}

template <int BN>
__global__ void __launch_bounds__(256) gemm_mma(
    const float* __restrict__ A, const float* __restrict__ W,
    const float* __restrict__ bias, float* __restrict__ C,
    int M, int N, int K)
{
    constexpr int NTW = BN / 16;
    extern __shared__ float smf[];
    const int tid = threadIdx.x;
    const int wid = tid >> 5, lane = tid & 31;
    const int g = lane >> 2, tg = lane & 3;
    const int wm = (wid & 3) * 32;
    const int wn = (wid >> 2) * (BN / 2);
    const int m0 = blockIdx.x * 128;
    const int n0 = blockIdx.y * BN;

    float acc[2][NTW][4];
#pragma unroll
    for (int mt = 0; mt < 2; mt++)
#pragma unroll
        for (int nt = 0; nt < NTW; nt++)
#pragma unroll
            for (int j = 0; j < 4; j++) acc[mt][nt][j] = 0.f;

    mma_mainloop<BN, NTW>(A, W, K, m0, n0, smf, smem_u32(smf),
                          tid, wid, lane, g, tg, wm, wn, acc);

#pragma unroll
    for (int mt = 0; mt < 2; mt++) {
#pragma unroll
        for (int nt = 0; nt < NTW; nt++) {
            int row = m0 + wm + mt * 16 + g;
            int col = n0 + wn + nt * 8 + 2 * tg;
            float b0 = __ldg(&bias[col]);
            float b1 = __ldg(&bias[col + 1]);
            float2 o0, o1;
            o0.x = fmaxf(acc[mt][nt][0] + b0, 0.f);
            o0.y = fmaxf(acc[mt][nt][1] + b1, 0.f);
            o1.x = fmaxf(acc[mt][nt][2] + b0, 0.f);
            o1.y = fmaxf(acc[mt][nt][3] + b1, 0.f);
            *reinterpret_cast<float2*>(C + (size_t)row * N + col) = o0;
            *reinterpret_cast<float2*>(C + (size_t)(row + 8) * N + col) = o1;
        }
    }
}

template <int BN, int PR>
__global__ void __launch_bounds__(256) gemm_mma_pool(
    const float* __restrict__ A, const float* __restrict__ W,
    const float* __restrict__ bias, float* __restrict__ dst,
    int M, int N, int K)
{
    constexpr int NTW = BN / 16;
    extern __shared__ float smf[];
    __shared__ float sbuf[4][BN];
    const int tid = threadIdx.x;
    const int wid = tid >> 5, lane = tid & 31;
    const int g = lane >> 2, tg = lane & 3;
    const int wm = (wid & 3) * 32;
    const int wn = (wid >> 2) * (BN / 2);
    const int m0 = blockIdx.x * 128;
    const int n0 = blockIdx.y * BN;

    float acc[2][NTW][4];
#pragma unroll
    for (int mt = 0; mt < 2; mt++)
#pragma unroll
        for (int nt = 0; nt < NTW; nt++)
#pragma unroll
            for (int j = 0; j < 4; j++) acc[mt][nt][j] = 0.f;

    mma_mainloop<BN, NTW>(A, W, K, m0, n0, smf, smem_u32(smf),
                          tid, wid, lane, g, tg, wm, wn, acc);

#pragma unroll
    for (int nt = 0; nt < NTW; nt++) {
        float v0 = fmaxf(fmaxf(acc[0][nt][0], acc[0][nt][2]),
                         fmaxf(acc[1][nt][0], acc[1][nt][2]));
        float v1 = fmaxf(fmaxf(acc[0][nt][1], acc[0][nt][3]),
                         fmaxf(acc[1][nt][1], acc[1][nt][3]));
#pragma unroll
        for (int off = 4; off < 32; off <<= 1) {
            v0 = fmaxf(v0, __shfl_xor_sync(0xffffffffu, v0, off));
            v1 = fmaxf(v1, __shfl_xor_sync(0xffffffffu, v1, off));
        }
        if (g == 0) {
            int lcol = wn + nt * 8 + 2 * tg;
            if (PR == 32) {
                int center = blockIdx.x * 4 + (wid & 3);
                int col = n0 + lcol;
                dst[(size_t)center * N + col] =
                    fmaxf(v0 + __ldg(&bias[col]), 0.f);
                dst[(size_t)center * N + col + 1] =
                    fmaxf(v1 + __ldg(&bias[col + 1]), 0.f);
            } else {
                sbuf[wid & 3][lcol] = v0;
                sbuf[wid & 3][lcol + 1] = v1;
            }
        }
    }
    if (PR == 128) {
        __syncthreads();
        if (tid < BN) {
            float m = fmaxf(fmaxf(sbuf[0][tid], sbuf[1][tid]),
                            fmaxf(sbuf[2][tid], sbuf[3][tid]));
            int col = n0 + tid;
            dst[(size_t)blockIdx.x * N + col] =
                fmaxf(m + __ldg(&bias[col]), 0.f);
        }
    }
}

// ---------------------------------------------------------------------------
// L2_0 fused: A gathered from f1 via g_g2 during prefetch.
// ---------------------------------------------------------------------------
__global__ void __launch_bounds__(256) gemm_l20_fused(
    const float* __restrict__ f1, const float* __restrict__ W,
    const float* __restrict__ bias, float* __restrict__ C)
{
    constexpr int BN = 128, NTW = 8, KTOT = 160;
    constexpr int SLOT = (128 + BN) * ST;
    extern __shared__ float smf[];
    int*   sbase = (int*)(smf + 2 * SLOT);
    float* sxyz  = smf + 2 * SLOT + 128;

    const int tid = threadIdx.x;
    const int wid = tid >> 5, lane = tid & 31;
    const int g = lane >> 2, tg = lane & 3;
    const int wm = (wid & 3) * 32;
    const int wn = (wid >> 2) * 64;
    const int m0 = blockIdx.x * 128;
    const uint32_t smbase = smem_u32(smf);

    if (tid < 128) {
        int R = m0 + tid;
        int c = R >> 5;
        int b = c >> 7;
        int j = g_g2[R];
        int fj = b * S1 + j;
        sbase[tid] = fj * 128;
        sxyz[tid * 4 + 0] = g_nx1[fj * 3 + 0] - g_nx2[c * 3 + 0];
        sxyz[tid * 4 + 1] = g_nx1[fj * 3 + 1] - g_nx2[c * 3 + 1];
        sxyz[tid * 4 + 2] = g_nx1[fj * 3 + 2] - g_nx2[c * 3 + 2];
    }
    __syncthreads();

    auto prefetch = [&](int kc, int s) {
        const uint32_t sb = smbase + (uint32_t)(s * SLOT) * 4u;
        if (kc < 4) {
#pragma unroll
            for (int i = 0; i < 4; i++) {
                int seg = tid + i * 256;
                int r = seg >> 3, c16 = seg & 7;
                cp16(sb + (uint32_t)(r * ST + c16 * 4) * 4u,
                     f1 + (size_t)sbase[r] + kc * 32 + c16 * 4);
            }
        } else {
            float* dstA = smf + s * SLOT;
            for (int idx = tid; idx < 128 * 32; idx += 256) {
                int r = idx >> 5, col = idx & 31;
                dstA[r * ST + col] = (col < 3) ? sxyz[r * 4 + col] : 0.f;
            }
        }
#pragma unroll
        for (int i = 0; i < 4; i++) {
            int seg = tid + i * 256;
            int r = seg >> 3, c16 = seg & 7;
            cp16(sb + (uint32_t)((128 + r) * ST + c16 * 4) * 4u,
                 W + (size_t)r * KTOT + kc * 32 + c16 * 4);
        }
    };

    float acc[2][NTW][4];
#pragma unroll
    for (int mt = 0; mt < 2; mt++)
#pragma unroll
        for (int nt = 0; nt < NTW; nt++)
#pragma unroll
            for (int j = 0; j < 4; j++) acc[mt][nt][j] = 0.f;

    prefetch(0, 0);
    CP_COMMIT();

    for (int kc = 0; kc < 5; kc++) {
        if (kc + 1 < 5) prefetch(kc + 1, (kc + 1) & 1);
        CP_COMMIT();
        CP_WAIT1();
        __syncthreads();

        const float* s_a = smf + (kc & 1) * SLOT;
        const float* s_w = s_a + 128 * ST;

#pragma unroll
        for (int grp = 0; grp < 2; grp++) {
            const int kb = grp * 16;
            uint32_t ah[2][4], al[2][4];
            frag_a_bf16(s_a, wm, g, tg, kb, ah, al);
#pragma unroll
            for (int nt = 0; nt < NTW; nt++) {
                int n = wn + nt * 8 + g;
                bfrag_mma_bf16(s_w, n, kb, tg, ah, al, acc[0][nt], acc[1][nt]);
            }
        }
        __syncthreads();
    }

#pragma unroll
    for (int mt = 0; mt < 2; mt++) {
#pragma unroll
        for (int nt = 0; nt < NTW; nt++) {
            int row = m0 + wm + mt * 16 + g;
            int col = wn + nt * 8 + 2 * tg;
            float b0 = __ldg(&bias[col]);
            float b1 = __ldg(&bias[col + 1]);
            float2 o0, o1;
            o0.x = fmaxf(acc[mt][nt][0] + b0, 0.f);
            o0.y = fmaxf(acc[mt][nt][1] + b1, 0.f);
            o1.x = fmaxf(acc[mt][nt][2] + b0, 0.f);
            o1.y = fmaxf(acc[mt][nt][3] + b1, 0.f);
            *reinterpret_cast<float2*>(C + (size_t)row * 128 + col) = o0;
            *reinterpret_cast<float2*>(C + (size_t)(row + 8) * 128 + col) = o1;
        }
    }
}

// ---------------------------------------------------------------------------
// BN=64 everywhere for generic GEMMs: 55KB smem + ~80 regs -> 4 CTAs/SM.
// ---------------------------------------------------------------------------
static void run_mma(const float* A, const float* W, const float* bias,
                    float* C, int M, int N, int K)
{
    const int smem = 2 * (128 + 64) * ST * 4;     // 55296
    cudaFuncSetAttribute(gemm_mma<64>,
                         cudaFuncAttributeMaxDynamicSharedMemorySize, smem);
    dim3 g(M / 128, N / 64);
    gemm_mma<64><<<g, 256, smem>>>(A, W, bias, C, M, N, K);
}

template <int PR>
static void run_mma_pool(const float* A, const float* W, const float* bias,
                         float* dst, int M, int N, int K)
{
    const int smem = 2 * (128 + 64) * ST * 4;     // 55296
    cudaFuncSetAttribute(gemm_mma_pool<64, PR>,
                         cudaFuncAttributeMaxDynamicSharedMemorySize, smem);
    dim3 g(M / 128, N / 64);
    gemm_mma_pool<64, PR><<<g, 256, smem>>>(A, W, bias, dst, M, N, K);
}

extern "C" void kernel_launch(void* const* d_in, const int* in_sizes, int n_in,
                              void* d_out, int out_size)
{
    (void)in_sizes; (void)n_in; (void)out_size;
    const float* data = (const float*)d_in[0];
    const float *w[9], *bi[9];
    for (int i = 0; i < 9; i++) {
        w[i]  = (const float*)d_in[1 + 2 * i];
        bi[i] = (const float*)d_in[2 + 2 * i];
    }

    float *scr0, *scr1, *f1, *f2, *nx1, *nx2, *x3, *w2p, *w3p;
    int *g2;
    cudaGetSymbolAddress((void**)&scr0, g_scr0);
    cudaGetSymbolAddress((void**)&scr1, g_scr1);
    cudaGetSymbolAddress((void**)&f1, g_f1);
    cudaGetSymbolAddress((void**)&f2, g_f2);
    cudaGetSymbolAddress((void**)&nx1, g_nx1);
    cudaGetSymbolAddress((void**)&nx2, g_nx2);
    cudaGetSymbolAddress((void**)&g2, g_g2);
    cudaGetSymbolAddress((void**)&x3, g_x3);
    cudaGetSymbolAddress((void**)&w2p, g_w2p);
    cudaGetSymbolAddress((void**)&w3p, g_w3p);

    const float R2a = (float)(0.2 * 0.2);
    const float R2b = (float)(0.4 * 0.4);

    padw2_reorder<<<(128 * 160 + 255) / 256, 256>>>(w[3], w2p);
    padw_kernel<<<(256 * 288 + 255) / 256, 256>>>(w[6], w3p, 256, 259, 288);

    // ---- Stage 1 ----
    fps_kernel<N1, S1, 512><<<BB, 512>>>(data, nx1);
    {
        const int smem = 3 * N1 * 4 + 32 * 32 * 4;   // 53248
        cudaFuncSetAttribute(ballq1_gather,
                             cudaFuncAttributeMaxDynamicSharedMemorySize, smem);
        ballq1_gather<<<BB * 8, 1024, smem>>>(data, nx1, R2a, scr1);
    }
    {
        const int smem = (2 * 128 * ST + 2 * 64 * ST + 128 * 4) * 4;  // 57344
        cudaFuncSetAttribute(gemm_l11_fused,
                             cudaFuncAttributeMaxDynamicSharedMemorySize, smem);
        gemm_l11_fused<<<(BB * S1 * NS) / 128, 256, smem>>>(
            scr1, w[0], bi[0], w[1], bi[1], scr0);
    }
    run_mma_pool<32>(scr0, w[2], bi[2], f1, BB * S1 * NS, 128, 64);

    // ---- Stage 2 ----
    fps2_ballq2<<<BB, 256>>>(nx1, nx2, R2b, g2);
    {
        const int smem = (2 * (128 + 128) * ST + 128 + 128 * 4) * 4;  // 76288
        cudaFuncSetAttribute(gemm_l20_fused,
                             cudaFuncAttributeMaxDynamicSharedMemorySize, smem);
        gemm_l20_fused<<<(BB * S2 * NS) / 128, 256, smem>>>(f1, w2p, bi[3], scr1);
    }
    run_mma(scr1, w[4], bi[4], scr0, BB * S2 * NS, 128, 128);
    run_mma_pool<32>(scr0, w[5], bi[5], f2, BB * S2 * NS, 256, 128);

    // ---- Stage 3 ----
    concat3_kernel<<<(BB * S2 * 288 + 255) / 256, 256>>>(x3);
    run_mma(x3, w3p, bi[6], scr0, BB * S2, 256, 288);
    run_mma(scr0, w[7], bi[7], scr1, BB * S2, 512, 256);
    run_mma_pool<128>(scr1, w[8], bi[8], (float*)d_out, BB * S2, 1024, 512);
}

// round 17
// speedup vs baseline: 1.1389x; 1.1389x over previous
#include <cuda_runtime.h>
#include <cuda_bf16.h>
#include <cstdint>

// ---------------------------------------------------------------------------
// PointNet++ encoder on GB300 (base sm_103 PTX: mma.sync + cp.async only).
// FPS / ball-query: exact fp32 (bitwise-match indices vs JAX ref).
// MLP: mma.sync m16n8k16 bf16, 3-term fp32 emulation (hi/lo bf16 split),
// cp.async double buffering, BN=128 tiles (best measured config, R14).
// Producer fusion: ballq1 emits gathered rows; K=3 layer fused into L1_1;
// stage-2 gather fused into L2_0 prefetch. Pools fused into final layers.
// R17: fps2_ballq2 + weight pads overlapped on a side stream (fork/join).
// ---------------------------------------------------------------------------

#define BB   32
#define N1   4096
#define S1   256
#define S2   128
#define NS   32
#define ST   40     // smem row stride (floats): conflict-free float2 frags

__device__ float g_scr0[262144 * 128];   // 134 MB
__device__ float g_scr1[262144 * 128];   // 134 MB
__device__ float g_f1[BB * S1 * 128];
__device__ float g_f2[BB * S2 * 256];
__device__ float g_nx1[BB * S1 * 3];
__device__ float g_nx2[BB * S2 * 3];
__device__ int   g_g2[BB * S2 * NS];
__device__ float g_x3[BB * S2 * 288];
__device__ float g_w2p[128 * 160];       // reordered [f128 | xyz3 | pad29]
__device__ float g_w3p[256 * 288];

__device__ __forceinline__ uint32_t smem_u32(const void* p) {
    uint32_t a;
    asm("{ .reg .u64 t; cvta.to.shared.u64 t, %1; cvt.u32.u64 %0, t; }"
        : "=r"(a) : "l"(p));
    return a;
}
__device__ __forceinline__ void cp16(uint32_t dst, const void* src) {
    asm volatile("cp.async.ca.shared.global [%0], [%1], 16;"
                 :: "r"(dst), "l"(src) : "memory");
}
#define CP_COMMIT() asm volatile("cp.async.commit_group;" ::: "memory")
#define CP_WAIT0()  asm volatile("cp.async.wait_group 0;" ::: "memory")
#define CP_WAIT1()  asm volatile("cp.async.wait_group 1;" ::: "memory")
#define CP_WAIT2()  asm volatile("cp.async.wait_group 2;" ::: "memory")

#define MMA_BF16(c, a, b0, b1)                                                \
    asm volatile(                                                             \
        "mma.sync.aligned.m16n8k16.row.col.f32.bf16.bf16.f32 "                \
        "{%0,%1,%2,%3}, {%4,%5,%6,%7}, {%8,%9}, {%0,%1,%2,%3};"               \
        : "+f"((c)[0]), "+f"((c)[1]), "+f"((c)[2]), "+f"((c)[3])              \
        : "r"((a)[0]), "r"((a)[1]), "r"((a)[2]), "r"((a)[3]),                 \
          "r"(b0), "r"(b1))

// Split a float pair into packed bf16x2 hi and lo (x in low half = even k).
__device__ __forceinline__ void split_pair(float x, float y,
                                           uint32_t& hi, uint32_t& lo)
{
    __nv_bfloat162 h = __floats2bfloat162_rn(x, y);
    float hx = __bfloat162float(__low2bfloat16(h));
    float hy = __bfloat162float(__high2bfloat16(h));
    __nv_bfloat162 l = __floats2bfloat162_rn(x - hx, y - hy);
    hi = *reinterpret_cast<uint32_t*>(&h);
    lo = *reinterpret_cast<uint32_t*>(&l);
}

// A fragment (m16n8k16, 2 m-tiles) for one k16 group starting at column kb.
__device__ __forceinline__ void frag_a_bf16(
    const float* s_a, int wm, int g, int tg, int kb,
    uint32_t ah[2][4], uint32_t al[2][4])
{
#pragma unroll
    for (int mt = 0; mt < 2; mt++) {
        int r0 = wm + mt * 16 + g;
        float2 p0 = *reinterpret_cast<const float2*>(&s_a[r0 * ST + kb + 2 * tg]);
        float2 p1 = *reinterpret_cast<const float2*>(&s_a[(r0 + 8) * ST + kb + 2 * tg]);
        float2 p2 = *reinterpret_cast<const float2*>(&s_a[r0 * ST + kb + 2 * tg + 8]);
        float2 p3 = *reinterpret_cast<const float2*>(&s_a[(r0 + 8) * ST + kb + 2 * tg + 8]);
        split_pair(p0.x, p0.y, ah[mt][0], al[mt][0]);
        split_pair(p1.x, p1.y, ah[mt][1], al[mt][1]);
        split_pair(p2.x, p2.y, ah[mt][2], al[mt][2]);
        split_pair(p3.x, p3.y, ah[mt][3], al[mt][3]);
    }
}

// B fragment split + 3-term emulated mma applied to both m-tiles.
__device__ __forceinline__ void bfrag_mma_bf16(
    const float* s_w, int n, int kb, int tg,
    const uint32_t ah[2][4], const uint32_t al[2][4],
    float* acc0, float* acc1)
{
    float2 q0 = *reinterpret_cast<const float2*>(&s_w[n * ST + kb + 2 * tg]);
    float2 q1 = *reinterpret_cast<const float2*>(&s_w[n * ST + kb + 2 * tg + 8]);
    uint32_t bh0, bl0, bh1, bl1;
    split_pair(q0.x, q0.y, bh0, bl0);
    split_pair(q1.x, q1.y, bh1, bl1);
    MMA_BF16(acc0, ah[0], bh0, bh1);
    MMA_BF16(acc0, ah[0], bl0, bl1);
    MMA_BF16(acc0, al[0], bh0, bh1);
    MMA_BF16(acc1, ah[1], bh0, bh1);
    MMA_BF16(acc1, ah[1], bl0, bl1);
    MMA_BF16(acc1, al[1], bh0, bh1);
}

// ---------------------------------------------------------------------------
// FPS stage 1 (bitwise exact vs reference)
// ---------------------------------------------------------------------------
template <int N, int NPTS, int THREADS>
__global__ void __launch_bounds__(THREADS) fps_kernel(
    const float* __restrict__ xyz_all, float* __restrict__ new_xyz)
{
    constexpr int PPT = N / THREADS;
    const int b = blockIdx.x;
    const int t = threadIdx.x;
    const float* xyz = xyz_all + (size_t)b * N * 3;

    float px[PPT], py[PPT], pz[PPT], md[PPT];
#pragma unroll
    for (int j = 0; j < PPT; j++) {
        int i = t + j * THREADS;
        px[j] = xyz[i * 3 + 0];
        py[j] = xyz[i * 3 + 1];
        pz[j] = xyz[i * 3 + 2];
        md[j] = 1e10f;
    }

    __shared__ unsigned long long wred[THREADS / 32];
    __shared__ int s_last;

    int last = 0;
    for (int it = 0; it < NPTS; it++) {
        float lx = __ldg(&xyz[last * 3 + 0]);
        float ly = __ldg(&xyz[last * 3 + 1]);
        float lz = __ldg(&xyz[last * 3 + 2]);
        if (t == 0) {
            float* o = new_xyz + (size_t)(b * NPTS + it) * 3;
            o[0] = lx; o[1] = ly; o[2] = lz;
        }
        unsigned long long best = 0ull;
#pragma unroll
        for (int j = 0; j < PPT; j++) {
            float dx = px[j] - lx, dy = py[j] - ly, dz = pz[j] - lz;
            float d = __fadd_rn(__fadd_rn(__fmul_rn(dx, dx), __fmul_rn(dy, dy)),
                                __fmul_rn(dz, dz));
            float m = fminf(md[j], d);
            md[j] = m;
            unsigned long long key =
                (((unsigned long long)__float_as_uint(m)) << 32) |
                (unsigned)(0xFFFFFFFFu - (unsigned)(t + j * THREADS));
            best = (key > best) ? key : best;
        }
#pragma unroll
        for (int off = 16; off > 0; off >>= 1) {
            unsigned long long o = __shfl_down_sync(0xffffffffu, best, off);
            best = (o > best) ? o : best;
        }
        if ((t & 31) == 0) wred[t >> 5] = best;
        __syncthreads();
        if (t < 32) {
            unsigned long long v = (t < THREADS / 32) ? wred[t] : 0ull;
#pragma unroll
            for (int off = 16; off > 0; off >>= 1) {
                unsigned long long o = __shfl_down_sync(0xffffffffu, v, off);
                v = (o > v) ? o : v;
            }
            if (t == 0)
                s_last = (int)(0xFFFFFFFFu - (unsigned)(v & 0xFFFFFFFFull));
        }
        __syncthreads();
        last = s_last;
    }
}

// ---------------------------------------------------------------------------
// Stage-1 ball query + gather
// ---------------------------------------------------------------------------
__global__ void __launch_bounds__(1024) ballq1_gather(
    const float* __restrict__ xyz_all, const float* __restrict__ centers,
    float R2, float* __restrict__ xg)
{
    extern __shared__ float sm[];
    float* sx = sm;
    float* sy = sm + N1;
    float* sz = sm + 2 * N1;
    int* buf = (int*)(sm + 3 * N1);          // [32][32]

    const int b = blockIdx.x >> 3;
    const int grp = blockIdx.x & 7;
    const float* xyz = xyz_all + (size_t)b * N1 * 3;
    for (int i = threadIdx.x; i < N1; i += 1024) {
        sx[i] = xyz[i * 3 + 0];
        sy[i] = xyz[i * 3 + 1];
        sz[i] = xyz[i * 3 + 2];
    }
    __syncthreads();

    const int wid = threadIdx.x >> 5, lane = threadIdx.x & 31;
    int* mybuf = buf + wid * 32;
    const int s = grp * 32 + wid;
    const int gw = b * S1 + s;
    const float cx = centers[gw * 3 + 0];
    const float cy = centers[gw * 3 + 1];
    const float cz = centers[gw * 3 + 2];
    int cnt = 0;
    for (int base = 0; base < N1; base += 32) {
        int p = base + lane;
        float dx = sx[p] - cx;
        float dy = sy[p] - cy;
        float dz = sz[p] - cz;
        float d2 = __fadd_rn(__fadd_rn(__fmul_rn(dx, dx), __fmul_rn(dy, dy)),
                             __fmul_rn(dz, dz));
        bool pred = d2 < R2;
        unsigned mask = __ballot_sync(0xffffffffu, pred);
        if (pred) {
            int pos = cnt + __popc(mask & ((1u << lane) - 1u));
            if (pos < NS) mybuf[pos] = p;
        }
        cnt += __popc(mask);
        if (cnt >= NS) break;
    }
    __syncwarp();
    int nv = cnt < NS ? cnt : NS;
    int first = (cnt > 0) ? mybuf[0] : 0;
    int val = (lane < nv) ? mybuf[lane] : first;
    float4 o;
    o.x = sx[val] - cx;
    o.y = sy[val] - cy;
    o.z = sz[val] - cz;
    o.w = 0.f;
    *reinterpret_cast<float4*>(xg + ((size_t)gw * 32 + lane) * 4) = o;
}

// ---------------------------------------------------------------------------
// Fused FPS stage 2 + ball query 2
// ---------------------------------------------------------------------------
__global__ void __launch_bounds__(256) fps2_ballq2(
    const float* __restrict__ xyz_all, float* __restrict__ new_xyz,
    float R2, int* __restrict__ out)
{
    __shared__ float s_px[S1], s_py[S1], s_pz[S1];
    __shared__ float s_cx[S2], s_cy[S2], s_cz[S2];
    __shared__ unsigned long long wred[8];
    __shared__ int s_last;
    __shared__ int buf[8][32];

    const int b = blockIdx.x;
    const int t = threadIdx.x;
    const float* xyz = xyz_all + (size_t)b * S1 * 3;

    float px = xyz[t * 3 + 0];
    float py = xyz[t * 3 + 1];
    float pz = xyz[t * 3 + 2];
    s_px[t] = px; s_py[t] = py; s_pz[t] = pz;
    float md = 1e10f;

    int last = 0;
    for (int it = 0; it < S2; it++) {
        float lx = __ldg(&xyz[last * 3 + 0]);
        float ly = __ldg(&xyz[last * 3 + 1]);
        float lz = __ldg(&xyz[last * 3 + 2]);
        if (t == 0) {
            float* o = new_xyz + (size_t)(b * S2 + it) * 3;
            o[0] = lx; o[1] = ly; o[2] = lz;
            s_cx[it] = lx; s_cy[it] = ly; s_cz[it] = lz;
        }
        float dx = px - lx, dy = py - ly, dz = pz - lz;
        float d = __fadd_rn(__fadd_rn(__fmul_rn(dx, dx), __fmul_rn(dy, dy)),
                            __fmul_rn(dz, dz));
        md = fminf(md, d);
        unsigned long long best =
            (((unsigned long long)__float_as_uint(md)) << 32) |
            (unsigned)(0xFFFFFFFFu - (unsigned)t);
#pragma unroll
        for (int off = 16; off > 0; off >>= 1) {
            unsigned long long o = __shfl_down_sync(0xffffffffu, best, off);
            best = (o > best) ? o : best;
        }
        if ((t & 31) == 0) wred[t >> 5] = best;
        __syncthreads();
        if (t < 32) {
            unsigned long long v = (t < 8) ? wred[t] : 0ull;
#pragma unroll
            for (int off = 16; off > 0; off >>= 1) {
                unsigned long long o = __shfl_down_sync(0xffffffffu, v, off);
                v = (o > v) ? o : v;
            }
            if (t == 0)
                s_last = (int)(0xFFFFFFFFu - (unsigned)(v & 0xFFFFFFFFull));
        }
        __syncthreads();
        last = s_last;
    }

    const int wid = t >> 5, lane = t & 31;
    int* mybuf = buf[wid];
    for (int ci = 0; ci < 16; ci++) {
        const int s = wid * 16 + ci;
        const float cx = s_cx[s], cy = s_cy[s], cz = s_cz[s];
        int cnt = 0;
        for (int base = 0; base < S1; base += 32) {
            int p = base + lane;
            float dx = s_px[p] - cx;
            float dy = s_py[p] - cy;
            float dz = s_pz[p] - cz;
            float d2 = __fadd_rn(__fadd_rn(__fmul_rn(dx, dx), __fmul_rn(dy, dy)),
                                 __fmul_rn(dz, dz));
            bool pred = d2 < R2;
            unsigned mask = __ballot_sync(0xffffffffu, pred);
            if (pred) {
                int pos = cnt + __popc(mask & ((1u << lane) - 1u));
                if (pos < NS) mybuf[pos] = p;
            }
            cnt += __popc(mask);
            if (cnt >= NS) break;
        }
        __syncwarp();
        int nv = cnt < NS ? cnt : NS;
        int first = (cnt > 0) ? mybuf[0] : 0;
        int val = (lane < nv) ? mybuf[lane] : first;
        out[((size_t)(b * S2 + s)) * NS + lane] = val;
        __syncwarp();
    }
}

// ---------------------------------------------------------------------------
// concat3 / weight pads
// ---------------------------------------------------------------------------
__global__ void concat3_kernel(float* __restrict__ x3)
{
    int t = blockIdx.x * blockDim.x + threadIdx.x;
    if (t >= BB * S2 * 288) return;
    int r = t / 288, col = t - r * 288;
    x3[t] = (col < 3) ? g_nx2[(size_t)r * 3 + col]
                      : (col < 259 ? g_f2[(size_t)r * 256 + (col - 3)] : 0.f);
}

__global__ void padw_kernel(const float* __restrict__ w, float* __restrict__ o,
                            int n, int kin, int kout)
{
    int t = blockIdx.x * blockDim.x + threadIdx.x;
    if (t >= n * kout) return;
    int r = t / kout, c = t - r * kout;
    o[t] = (c < kin) ? w[r * kin + c] : 0.f;
}

__global__ void padw2_reorder(const float* __restrict__ w, float* __restrict__ o)
{
    int t = blockIdx.x * blockDim.x + threadIdx.x;
    if (t >= 128 * 160) return;
    int r = t / 160, c = t - r * 160;
    float v = 0.f;
    if (c < 128)      v = w[r * 131 + 3 + c];
    else if (c < 131) v = w[r * 131 + (c - 128)];
    o[t] = v;
}

// ---------------------------------------------------------------------------
// L1_1 fused
// ---------------------------------------------------------------------------
__global__ void __launch_bounds__(256) gemm_l11_fused(
    const float* __restrict__ xg,
    const float* __restrict__ w0, const float* __restrict__ b0,
    const float* __restrict__ w1, const float* __restrict__ b1,
    float* __restrict__ C)
{
    extern __shared__ float smf[];
    float* s_A = smf;
    float* s_W = smf + 2 * 128 * ST;
    float* s_x = s_W + 2 * 64 * ST;

    const int tid = threadIdx.x;
    const int wid = tid >> 5, lane = tid & 31;
    const int g = lane >> 2, tg = lane & 3;
    const int wm = (wid & 3) * 32;
    const int wn = (wid >> 2) * 32;
    const int m0 = blockIdx.x * 128;
    const uint32_t smbase = smem_u32(smf);
    const uint32_t sxoff = (uint32_t)(2 * 128 * ST + 2 * 64 * ST) * 4u;

    if (tid < 128)
        cp16(smbase + sxoff + (uint32_t)tid * 16u, xg + (size_t)(m0 + tid) * 4);
    CP_COMMIT();
#pragma unroll
    for (int kc = 0; kc < 2; kc++) {
#pragma unroll
        for (int i = 0; i < 2; i++) {
            int seg = tid + i * 256;
            int r = seg >> 3, c16 = seg & 7;
            cp16(smbase + (uint32_t)((2 * 128 * ST + kc * 64 * ST) + r * ST + c16 * 4) * 4u,
                 w1 + (size_t)r * 64 + kc * 32 + c16 * 4);
        }
        CP_COMMIT();
    }

    CP_WAIT2();
    __syncthreads();

    for (int idx = tid; idx < 128 * 64; idx += 256) {
        int r = idx >> 6, o = idx & 63;
        const float* xr = s_x + r * 4;
        float acc = 0.f;
        acc = fmaf(xr[0], __ldg(&w0[o * 3 + 0]), acc);
        acc = fmaf(xr[1], __ldg(&w0[o * 3 + 1]), acc);
        acc = fmaf(xr[2], __ldg(&w0[o * 3 + 2]), acc);
        s_A[(o >> 5) * 128 * ST + r * ST + (o & 31)] =
            fmaxf(acc + __ldg(&b0[o]), 0.f);
    }

    float acc[2][4][4];
#pragma unroll
    for (int mt = 0; mt < 2; mt++)
#pragma unroll
        for (int nt = 0; nt < 4; nt++)
#pragma unroll
            for (int j = 0; j < 4; j++) acc[mt][nt][j] = 0.f;

#pragma unroll
    for (int kc = 0; kc < 2; kc++) {
        if (kc == 0) { CP_WAIT1(); } else { CP_WAIT0(); }
        __syncthreads();
        const float* s_a = s_A + kc * 128 * ST;
        const float* s_w = s_W + kc * 64 * ST;
#pragma unroll
        for (int grp = 0; grp < 2; grp++) {
            const int kb = grp * 16;
            uint32_t ah[2][4], al[2][4];
            frag_a_bf16(s_a, wm, g, tg, kb, ah, al);
#pragma unroll
            for (int nt = 0; nt < 4; nt++) {
                int n = wn + nt * 8 + g;
                bfrag_mma_bf16(s_w, n, kb, tg, ah, al, acc[0][nt], acc[1][nt]);
            }
        }
        __syncthreads();
    }

#pragma unroll
    for (int mt = 0; mt < 2; mt++) {
#pragma unroll
        for (int nt = 0; nt < 4; nt++) {
            int row = m0 + wm + mt * 16 + g;
            int col = wn + nt * 8 + 2 * tg;
            float b0v = __ldg(&b1[col]);
            float b1v = __ldg(&b1[col + 1]);
            float2 o0, o1;
            o0.x = fmaxf(acc[mt][nt][0] + b0v, 0.f);
            o0.y = fmaxf(acc[mt][nt][1] + b1v, 0.f);
            o1.x = fmaxf(acc[mt][nt][2] + b0v, 0.f);
            o1.y = fmaxf(acc[mt][nt][3] + b1v, 0.f);
            *reinterpret_cast<float2*>(C + (size_t)row * 64 + col) = o0;
            *reinterpret_cast<float2*>(C + (size_t)(row + 8) * 64 + col) = o1;
        }
    }
}

// ---------------------------------------------------------------------------
// Generic mma mainloop (cp.async double-buffered), CTA tile 128 x BN, BK=32.
// ---------------------------------------------------------------------------
template <int BN, int NTW>
__device__ __forceinline__ void mma_mainloop(
    const float* __restrict__ A, const float* __restrict__ W,
    int K, int m0, int n0, float* smf, uint32_t smbase,
    int tid, int wid, int lane, int g, int tg, int wm, int wn,
    float acc[2][NTW][4])
{
    constexpr int SLOT = (128 + BN) * ST;
    const int KC = K >> 5;

    auto prefetch = [&](int kc, int s) {
        const uint32_t sb = smbase + (uint32_t)(s * SLOT) * 4u;
#pragma unroll
        for (int i = 0; i < 4; i++) {
            int seg = tid + i * 256;
            int r = seg >> 3, c16 = seg & 7;
            cp16(sb + (uint32_t)(r * ST + c16 * 4) * 4u,
                 A + (size_t)(m0 + r) * K + kc * 32 + c16 * 4);
        }
#pragma unroll
        for (int i = 0; i < BN / 32; i++) {
            int seg = tid + i * 256;
            int r = seg >> 3, c16 = seg & 7;
            cp16(sb + (uint32_t)((128 + r) * ST + c16 * 4) * 4u,
                 W + (size_t)(n0 + r) * K + kc * 32 + c16 * 4);
        }
    };

    prefetch(0, 0);
    CP_COMMIT();

    for (int kc = 0; kc < KC; kc++) {
        if (kc + 1 < KC) prefetch(kc + 1, (kc + 1) & 1);
        CP_COMMIT();
        CP_WAIT1();
        __syncthreads();

        const float* s_a = smf + (kc & 1) * SLOT;
        const float* s_w = s_a + 128 * ST;

#pragma unroll
        for (int grp = 0; grp < 2; grp++) {
            const int kb = grp * 16;
            uint32_t ah[2][4], al[2][4];
            frag_a_bf16(s_a, wm, g, tg, kb, ah, al);
#pragma unroll
            for (int nt = 0; nt < NTW; nt++) {
                int n = wn + nt * 8 + g;
                bfrag_mma_bf16(s_w, n, kb, tg, ah, al, acc[0][nt], acc[1][nt]);
            }
        }
        __syncthreads();
    }
}

template <int BN>
__global__ void __launch_bounds__(256) gemm_mma(
    const float* __restrict__ A, const float* __restrict__ W,
    const float* __restrict__ bias, float* __restrict__ C,
    int M, int N, int K)
{
    constexpr int NTW = BN / 16;
    extern __shared__ float smf[];
    const int tid = threadIdx.x;
    const int wid = tid >> 5, lane = tid & 31;
    const int g = lane >> 2, tg = lane & 3;
    const int wm = (wid & 3) * 32;
    const int wn = (wid >> 2) * (BN / 2);
    const int m0 = blockIdx.x * 128;
    const int n0 = blockIdx.y * BN;

    float acc[2][NTW][4];
#pragma unroll
    for (int mt = 0; mt < 2; mt++)
#pragma unroll
        for (int nt = 0; nt < NTW; nt++)
#pragma unroll
            for (int j = 0; j < 4; j++) acc[mt][nt][j] = 0.f;

    mma_mainloop<BN, NTW>(A, W, K, m0, n0, smf, smem_u32(smf),
                          tid, wid, lane, g, tg, wm, wn, acc);

#pragma unroll
    for (int mt = 0; mt < 2; mt++) {
#pragma unroll
        for (int nt = 0; nt < NTW; nt++) {
            int row = m0 + wm + mt * 16 + g;
            int col = n0 + wn + nt * 8 + 2 * tg;
            float b0 = __ldg(&bias[col]);
            float b1 = __ldg(&bias[col + 1]);
            float2 o0, o1;
            o0.x = fmaxf(acc[mt][nt][0] + b0, 0.f);
            o0.y = fmaxf(acc[mt][nt][1] + b1, 0.f);
            o1.x = fmaxf(acc[mt][nt][2] + b0, 0.f);
            o1.y = fmaxf(acc[mt][nt][3] + b1, 0.f);
            *reinterpret_cast<float2*>(C + (size_t)row * N + col) = o0;
            *reinterpret_cast<float2*>(C + (size_t)(row + 8) * N + col) = o1;
        }
    }
}

template <int BN, int PR>
__global__ void __launch_bounds__(256) gemm_mma_pool(
    const float* __restrict__ A, const float* __restrict__ W,
    const float* __restrict__ bias, float* __restrict__ dst,
    int M, int N, int K)
{
    constexpr int NTW = BN / 16;
    extern __shared__ float smf[];
    __shared__ float sbuf[4][BN];
    const int tid = threadIdx.x;
    const int wid = tid >> 5, lane = tid & 31;
    const int g = lane >> 2, tg = lane & 3;
    const int wm = (wid & 3) * 32;
    const int wn = (wid >> 2) * (BN / 2);
    const int m0 = blockIdx.x * 128;
    const int n0 = blockIdx.y * BN;

    float acc[2][NTW][4];
#pragma unroll
    for (int mt = 0; mt < 2; mt++)
#pragma unroll
        for (int nt = 0; nt < NTW; nt++)
#pragma unroll
            for (int j = 0; j < 4; j++) acc[mt][nt][j] = 0.f;

    mma_mainloop<BN, NTW>(A, W, K, m0, n0, smf, smem_u32(smf),
                          tid, wid, lane, g, tg, wm, wn, acc);

#pragma unroll
    for (int nt = 0; nt < NTW; nt++) {
        float v0 = fmaxf(fmaxf(acc[0][nt][0], acc[0][nt][2]),
                         fmaxf(acc[1][nt][0], acc[1][nt][2]));
        float v1 = fmaxf(fmaxf(acc[0][nt][1], acc[0][nt][3]),
                         fmaxf(acc[1][nt][1], acc[1][nt][3]));
#pragma unroll
        for (int off = 4; off < 32; off <<= 1) {
            v0 = fmaxf(v0, __shfl_xor_sync(0xffffffffu, v0, off));
            v1 = fmaxf(v1, __shfl_xor_sync(0xffffffffu, v1, off));
        }
        if (g == 0) {
            int lcol = wn + nt * 8 + 2 * tg;
            if (PR == 32) {
                int center = blockIdx.x * 4 + (wid & 3);
                int col = n0 + lcol;
                dst[(size_t)center * N + col] =
                    fmaxf(v0 + __ldg(&bias[col]), 0.f);
                dst[(size_t)center * N + col + 1] =
                    fmaxf(v1 + __ldg(&bias[col + 1]), 0.f);
            } else {
                sbuf[wid & 3][lcol] = v0;
                sbuf[wid & 3][lcol + 1] = v1;
            }
        }
    }
    if (PR == 128) {
        __syncthreads();
        if (tid < BN) {
            float m = fmaxf(fmaxf(sbuf[0][tid], sbuf[1][tid]),
                            fmaxf(sbuf[2][tid], sbuf[3][tid]));
            int col = n0 + tid;
            dst[(size_t)blockIdx.x * N + col] =
                fmaxf(m + __ldg(&bias[col]), 0.f);
        }
    }
}

// ---------------------------------------------------------------------------
// L2_0 fused: A gathered from f1 via g_g2 during prefetch.
// ---------------------------------------------------------------------------
__global__ void __launch_bounds__(256) gemm_l20_fused(
    const float* __restrict__ f1, const float* __restrict__ W,
    const float* __restrict__ bias, float* __restrict__ C)
{
    constexpr int BN = 128, NTW = 8, KTOT = 160;
    constexpr int SLOT = (128 + BN) * ST;
    extern __shared__ float smf[];
    int*   sbase = (int*)(smf + 2 * SLOT);
    float* sxyz  = smf + 2 * SLOT + 128;

    const int tid = threadIdx.x;
    const int wid = tid >> 5, lane = tid & 31;
    const int g = lane >> 2, tg = lane & 3;
    const int wm = (wid & 3) * 32;
    const int wn = (wid >> 2) * 64;
    const int m0 = blockIdx.x * 128;
    const uint32_t smbase = smem_u32(smf);

    if (tid < 128) {
        int R = m0 + tid;
        int c = R >> 5;
        int b = c >> 7;
        int j = g_g2[R];
        int fj = b * S1 + j;
        sbase[tid] = fj * 128;
        sxyz[tid * 4 + 0] = g_nx1[fj * 3 + 0] - g_nx2[c * 3 + 0];
        sxyz[tid * 4 + 1] = g_nx1[fj * 3 + 1] - g_nx2[c * 3 + 1];
        sxyz[tid * 4 + 2] = g_nx1[fj * 3 + 2] - g_nx2[c * 3 + 2];
    }
    __syncthreads();

    auto prefetch = [&](int kc, int s) {
        const uint32_t sb = smbase + (uint32_t)(s * SLOT) * 4u;
        if (kc < 4) {
#pragma unroll
            for (int i = 0; i < 4; i++) {
                int seg = tid + i * 256;
                int r = seg >> 3, c16 = seg & 7;
                cp16(sb + (uint32_t)(r * ST + c16 * 4) * 4u,
                     f1 + (size_t)sbase[r] + kc * 32 + c16 * 4);
            }
        } else {
            float* dstA = smf + s * SLOT;
            for (int idx = tid; idx < 128 * 32; idx += 256) {
                int r = idx >> 5, col = idx & 31;
                dstA[r * ST + col] = (col < 3) ? sxyz[r * 4 + col] : 0.f;
            }
        }
#pragma unroll
        for (int i = 0; i < 4; i++) {
            int seg = tid + i * 256;
            int r = seg >> 3, c16 = seg & 7;
            cp16(sb + (uint32_t)((128 + r) * ST + c16 * 4) * 4u,
                 W + (size_t)r * KTOT + kc * 32 + c16 * 4);
        }
    };

    float acc[2][NTW][4];
#pragma unroll
    for (int mt = 0; mt < 2; mt++)
#pragma unroll
        for (int nt = 0; nt < NTW; nt++)
#pragma unroll
            for (int j = 0; j < 4; j++) acc[mt][nt][j] = 0.f;

    prefetch(0, 0);
    CP_COMMIT();

    for (int kc = 0; kc < 5; kc++) {
        if (kc + 1 < 5) prefetch(kc + 1, (kc + 1) & 1);
        CP_COMMIT();
        CP_WAIT1();
        __syncthreads();

        const float* s_a = smf + (kc & 1) * SLOT;
        const float* s_w = s_a + 128 * ST;

#pragma unroll
        for (int grp = 0; grp < 2; grp++) {
            const int kb = grp * 16;
            uint32_t ah[2][4], al[2][4];
            frag_a_bf16(s_a, wm, g, tg, kb, ah, al);
#pragma unroll
            for (int nt = 0; nt < NTW; nt++) {
                int n = wn + nt * 8 + g;
                bfrag_mma_bf16(s_w, n, kb, tg, ah, al, acc[0][nt], acc[1][nt]);
            }
        }
        __syncthreads();
    }

#pragma unroll
    for (int mt = 0; mt < 2; mt++) {
#pragma unroll
        for (int nt = 0; nt < NTW; nt++) {
            int row = m0 + wm + mt * 16 + g;
            int col = wn + nt * 8 + 2 * tg;
            float b0 = __ldg(&bias[col]);
            float b1 = __ldg(&bias[col + 1]);
            float2 o0, o1;
            o0.x = fmaxf(acc[mt][nt][0] + b0, 0.f);
            o0.y = fmaxf(acc[mt][nt][1] + b1, 0.f);
            o1.x = fmaxf(acc[mt][nt][2] + b0, 0.f);
            o1.y = fmaxf(acc[mt][nt][3] + b1, 0.f);
            *reinterpret_cast<float2*>(C + (size_t)row * 128 + col) = o0;
            *reinterpret_cast<float2*>(C + (size_t)(row + 8) * 128 + col) = o1;
        }
    }
}

// ---------------------------------------------------------------------------
static void run_mma(const float* A, const float* W, const float* bias,
                    float* C, int M, int N, int K)
{
    if (N % 128 == 0) {
        const int smem = 2 * (128 + 128) * ST * 4;    // 81920
        cudaFuncSetAttribute(gemm_mma<128>,
                             cudaFuncAttributeMaxDynamicSharedMemorySize, smem);
        dim3 g(M / 128, N / 128);
        gemm_mma<128><<<g, 256, smem>>>(A, W, bias, C, M, N, K);
    } else {
        const int smem = 2 * (128 + 64) * ST * 4;     // 61440
        cudaFuncSetAttribute(gemm_mma<64>,
                             cudaFuncAttributeMaxDynamicSharedMemorySize, smem);
        dim3 g(M / 128, N / 64);
        gemm_mma<64><<<g, 256, smem>>>(A, W, bias, C, M, N, K);
    }
}

template <int PR>
static void run_mma_pool(const float* A, const float* W, const float* bias,
                         float* dst, int M, int N, int K)
{
    const int smem = 2 * (128 + 128) * ST * 4;
    cudaFuncSetAttribute(gemm_mma_pool<128, PR>,
                         cudaFuncAttributeMaxDynamicSharedMemorySize, smem);
    dim3 g(M / 128, N / 128);
    gemm_mma_pool<128, PR><<<g, 256, smem>>>(A, W, bias, dst, M, N, K);
}

extern "C" void kernel_launch(void* const* d_in, const int* in_sizes, int n_in,
                              void* d_out, int out_size)
{
    (void)in_sizes; (void)n_in; (void)out_size;
    const float* data = (const float*)d_in[0];
    const float *w[9], *bi[9];
    for (int i = 0; i < 9; i++) {
        w[i]  = (const float*)d_in[1 + 2 * i];
        bi[i] = (const float*)d_in[2 + 2 * i];
    }

    float *scr0, *scr1, *f1, *f2, *nx1, *nx2, *x3, *w2p, *w3p;
    int *g2;
    cudaGetSymbolAddress((void**)&scr0, g_scr0);
    cudaGetSymbolAddress((void**)&scr1, g_scr1);
    cudaGetSymbolAddress((void**)&f1, g_f1);
    cudaGetSymbolAddress((void**)&f2, g_f2);
    cudaGetSymbolAddress((void**)&nx1, g_nx1);
    cudaGetSymbolAddress((void**)&nx2, g_nx2);
    cudaGetSymbolAddress((void**)&g2, g_g2);
    cudaGetSymbolAddress((void**)&x3, g_x3);
    cudaGetSymbolAddress((void**)&w2p, g_w2p);
    cudaGetSymbolAddress((void**)&w3p, g_w3p);

    const float R2a = (float)(0.2 * 0.2);
    const float R2b = (float)(0.4 * 0.4);

    // side stream + events (host-side handles, created once; no device mem)
    static cudaStream_t s2 = nullptr;
    static cudaEvent_t evA = nullptr, evB = nullptr;
    if (s2 == nullptr) {
        cudaStreamCreateWithFlags(&s2, cudaStreamNonBlocking);
        cudaEventCreateWithFlags(&evA, cudaEventDisableTiming);
        cudaEventCreateWithFlags(&evB, cudaEventDisableTiming);
    }

    // ---- Stage 1 (main stream) ----
    fps_kernel<N1, S1, 512><<<BB, 512>>>(data, nx1);

    // fork: side stream runs fps2_ballq2 (needs only nx1) + weight pads
    cudaEventRecord(evA, 0);
    cudaStreamWaitEvent(s2, evA, 0);
    padw2_reorder<<<(128 * 160 + 255) / 256, 256, 0, s2>>>(w[3], w2p);
    padw_kernel<<<(256 * 288 + 255) / 256, 256, 0, s2>>>(w[6], w3p, 256, 259, 288);
    fps2_ballq2<<<BB, 256, 0, s2>>>(nx1, nx2, R2b, g2);
    cudaEventRecord(evB, s2);

    {
        const int smem = 3 * N1 * 4 + 32 * 32 * 4;   // 53248
        cudaFuncSetAttribute(ballq1_gather,
                             cudaFuncAttributeMaxDynamicSharedMemorySize, smem);
        ballq1_gather<<<BB * 8, 1024, smem>>>(data, nx1, R2a, scr1);
    }
    {
        const int smem = (2 * 128 * ST + 2 * 64 * ST + 128 * 4) * 4;  // 63488
        cudaFuncSetAttribute(gemm_l11_fused,
                             cudaFuncAttributeMaxDynamicSharedMemorySize, smem);
        gemm_l11_fused<<<(BB * S1 * NS) / 128, 256, smem>>>(
            scr1, w[0], bi[0], w[1], bi[1], scr0);
    }
    run_mma_pool<32>(scr0, w[2], bi[2], f1, BB * S1 * NS, 128, 64);

    // join: stage-2 needs g2 / nx2 / w2p from the side stream
    cudaStreamWaitEvent(0, evB, 0);

    // ---- Stage 2 ----
    {
        const int smem = (2 * (128 + 128) * ST + 128 + 128 * 4) * 4;  // 84480
        cudaFuncSetAttribute(gemm_l20_fused,
                             cudaFuncAttributeMaxDynamicSharedMemorySize, smem);
        gemm_l20_fused<<<(BB * S2 * NS) / 128, 256, smem>>>(f1, w2p, bi[3], scr1);
    }
    run_mma(scr1, w[4], bi[4], scr0, BB * S2 * NS, 128, 128);
    run_mma_pool<32>(scr0, w[5], bi[5], f2, BB * S2 * NS, 256, 128);

    // ---- Stage 3 ----
    concat3_kernel<<<(BB * S2 * 288 + 255) / 256, 256>>>(x3);
    run_mma(x3, w3p, bi[6], scr0, BB * S2, 256, 288);
    run_mma(scr0, w[7], bi[7], scr1, BB * S2, 512, 256);
    run_mma_pool<128>(scr1, w[8], bi[8], (float*)d_out, BB * S2, 1024, 512);
}